// round 1
// baseline (speedup 1.0000x reference)
#include <cuda_runtime.h>
#include <math.h>

// Problem constants
#define BB      4
#define TT      2048
#define HID     1024
#define NH      8
#define HD      128
#define KS      4
#define INTER   2816
#define MROWS   (BB * TT)            // 8192
#define NCHUNK  16                   // T / 128
#define CLEN    128

// ---------------- scratch (single __device__ array, offsets in floats) ----
static const size_t SZ_MH = (size_t)MROWS * HID;      // 8388608
static const size_t SZ_MI = (size_t)MROWS * INTER;    // 23068672

static const size_t OFF_H     = 0;
static const size_t OFF_QKV   = OFF_H     + SZ_MH;        // 3*SZ_MH
static const size_t OFF_CONV  = OFF_QKV   + 3 * SZ_MH;
static const size_t OFF_LOCAL = OFF_CONV  + SZ_MH;
static const size_t OFF_RKS   = OFF_LOCAL + SZ_MH;
static const size_t OFF_RKV   = OFF_RKS   + SZ_MH;
static const size_t OFF_O     = OFF_RKV   + SZ_MH;
static const size_t OFF_TMP   = OFF_O     + SZ_MH;
static const size_t OFF_O2    = OFF_TMP   + SZ_MH;
static const size_t OFF_ATTN  = OFF_O2    + SZ_MH;
static const size_t OFF_X1    = OFF_ATTN  + SZ_MH;
static const size_t OFF_H2    = OFF_X1    + SZ_MH;
static const size_t OFF_FFA   = OFF_H2    + SZ_MH;
static const size_t OFF_FFB   = OFF_FFA   + SZ_MI;
static const size_t OFF_FFN   = OFF_FFB   + SZ_MI;
static const size_t OFF_CKS   = OFF_FFN   + SZ_MH;        // carries: B*NCHUNK*HID = 65536 each
static const size_t OFF_CKV   = OFF_CKS   + 65536;
static const size_t OFF_PKS   = OFF_CKV   + 65536;
static const size_t OFF_PKV   = OFF_PKS   + 65536;
static const size_t SCRATCH_FLOATS = OFF_PKV + 65536;     // ~172.2M floats (~689MB)

__device__ float g_scratch[SCRATCH_FLOATS];

// ---------------- helpers ----------------
__device__ __forceinline__ float sigmoidf_(float x) { return 1.0f / (1.0f + expf(-x)); }
__device__ __forceinline__ float siluf_(float x)    { return x / (1.0f + expf(-x)); }

// ---------------- rmsnorm: one block (256 thr) per row of 1024 ------------
__global__ void rmsnorm_kernel(const float* __restrict__ x, const float* __restrict__ w,
                               float* __restrict__ o) {
    int row = blockIdx.x;
    size_t base = (size_t)row * HID;
    float4 v = ((const float4*)(x + base))[threadIdx.x];
    float ss = v.x * v.x + v.y * v.y + v.z * v.z + v.w * v.w;
    __shared__ float sred[8];
    int lane = threadIdx.x & 31, wid = threadIdx.x >> 5;
    #pragma unroll
    for (int k = 16; k; k >>= 1) ss += __shfl_xor_sync(0xFFFFFFFFu, ss, k);
    if (lane == 0) sred[wid] = ss;
    __syncthreads();
    if (wid == 0) {
        float t = (lane < 8) ? sred[lane] : 0.0f;
        #pragma unroll
        for (int k = 4; k; k >>= 1) t += __shfl_xor_sync(0xFFFFFFFFu, t, k);
        if (lane == 0) sred[0] = t;
    }
    __syncthreads();
    float scale = rsqrtf(sred[0] * (1.0f / (float)HID) + 1e-6f);
    float4 wv = ((const float4*)w)[threadIdx.x];
    float4 r = make_float4(v.x * scale * wv.x, v.y * scale * wv.y,
                           v.z * scale * wv.z, v.w * scale * wv.w);
    ((float4*)(o + base))[threadIdx.x] = r;
}

// ---------------- SGEMM: C[M,N](ldC) = A[M,K](ldA) @ W[N,K](ldW)^T --------
// 128x128 block tile, K-tile 16, 256 threads, 8x8 per thread.
template <bool ACC>
__global__ __launch_bounds__(256, 2)
void sgemm_kernel(const float* __restrict__ A, int ldA,
                  const float* __restrict__ W, int ldW,
                  float* __restrict__ C, int ldC, int K) {
    __shared__ float As[16][132];
    __shared__ float Bs[16][132];
    int tid = threadIdx.x;
    int tx = tid & 15, ty = tid >> 4;
    int m0 = blockIdx.y * 128, n0 = blockIdx.x * 128;
    const float* Ag = A + (size_t)m0 * ldA;
    const float* Wg = W + (size_t)n0 * ldW;
    float acc[8][8];
    #pragma unroll
    for (int i = 0; i < 8; i++)
        #pragma unroll
        for (int j = 0; j < 8; j++) acc[i][j] = 0.0f;

    for (int k0 = 0; k0 < K; k0 += 16) {
        #pragma unroll
        for (int u = 0; u < 2; u++) {
            int v  = tid + u * 256;
            int r  = v >> 2;
            int c4 = (v & 3) * 4;
            float4 a = *(const float4*)(Ag + (size_t)r * ldA + k0 + c4);
            As[c4 + 0][r] = a.x; As[c4 + 1][r] = a.y;
            As[c4 + 2][r] = a.z; As[c4 + 3][r] = a.w;
            float4 b = *(const float4*)(Wg + (size_t)r * ldW + k0 + c4);
            Bs[c4 + 0][r] = b.x; Bs[c4 + 1][r] = b.y;
            Bs[c4 + 2][r] = b.z; Bs[c4 + 3][r] = b.w;
        }
        __syncthreads();
        #pragma unroll
        for (int kk = 0; kk < 16; kk++) {
            float a[8], b[8];
            #pragma unroll
            for (int i = 0; i < 8; i++) a[i] = As[kk][ty * 8 + i];
            #pragma unroll
            for (int j = 0; j < 8; j++) b[j] = Bs[kk][tx * 8 + j];
            #pragma unroll
            for (int i = 0; i < 8; i++)
                #pragma unroll
                for (int j = 0; j < 8; j++) acc[i][j] += a[i] * b[j];
        }
        __syncthreads();
    }

    float* Cg = C + (size_t)(m0 + ty * 8) * ldC + n0 + tx * 8;
    #pragma unroll
    for (int i = 0; i < 8; i++) {
        float4 r0 = make_float4(acc[i][0], acc[i][1], acc[i][2], acc[i][3]);
        float4 r1 = make_float4(acc[i][4], acc[i][5], acc[i][6], acc[i][7]);
        float4* p0 = (float4*)(Cg + (size_t)i * ldC);
        float4* p1 = (float4*)(Cg + (size_t)i * ldC + 4);
        if (ACC) {
            float4 o0 = *p0, o1 = *p1;
            r0.x += o0.x; r0.y += o0.y; r0.z += o0.z; r0.w += o0.w;
            r1.x += o1.x; r1.y += o1.y; r1.z += o1.z; r1.w += o1.w;
        }
        *p0 = r0; *p1 = r1;
    }
}

// ---------------- depthwise causal conv (KS=4) + bias + silu --------------
__global__ void conv_silu_kernel(const float* __restrict__ h, const float* __restrict__ cw,
                                 const float* __restrict__ cb, float* __restrict__ o) {
    size_t idx = (size_t)blockIdx.x * blockDim.x + threadIdx.x;   // over M*HID
    int c = idx & (HID - 1);
    int t = (int)((idx >> 10) & (TT - 1));
    int b = (int)(idx >> 21);
    float acc = cb[c];
    #pragma unroll
    for (int j = 0; j < KS; j++) {
        int tt = t + j - (KS - 1);
        if (tt >= 0) acc += h[((size_t)(b * TT + tt)) * HID + c] * cw[c * KS + j];
    }
    o[idx] = siluf_(acc);
}

// ---------------- elu(x)+1 applied in place to q,k cols of qkv ------------
__global__ void eluqk_kernel(float* __restrict__ qkv) {
    size_t idx = (size_t)blockIdx.x * blockDim.x + threadIdx.x;   // over M*2048
    size_t row = idx >> 11;
    int col = (int)(idx & 2047);
    float* p = qkv + row * 3072 + col;
    float v = *p;
    *p = (v > 0.0f) ? (v + 1.0f) : expf(v);
}

// ---------------- scan pass A: per-chunk local recurrence -----------------
__global__ void scan_chunk_kernel(const float* __restrict__ qkv, const float* __restrict__ dp,
                                  float* __restrict__ rks, float* __restrict__ rkv,
                                  float* __restrict__ cks, float* __restrict__ ckv) {
    int c = blockIdx.x * blockDim.x + threadIdx.x;   // 0..1023
    int j = blockIdx.y;                               // chunk
    int b = blockIdx.z;
    float d = sigmoidf_(dp[c >> 7]);
    float sks = 0.0f, skv = 0.0f;
    size_t base  = ((size_t)(b * TT + j * CLEN)) * 3072 + c;
    size_t obase = ((size_t)(b * TT + j * CLEN)) * HID + c;
    for (int i = 0; i < CLEN; i++) {
        float kk = qkv[base + 1024];
        float vv = qkv[base + 2048];
        sks = d * sks + kk;
        skv = d * skv + kk * vv;
        rks[obase] = sks;
        rkv[obase] = skv;
        base += 3072; obase += HID;
    }
    cks[(b * NCHUNK + j) * HID + c] = sks;
    ckv[(b * NCHUNK + j) * HID + c] = skv;
}

// ---------------- scan pass B: carry propagation across 16 chunks ---------
__global__ void scan_carry_kernel(const float* __restrict__ dp,
                                  const float* __restrict__ cks, const float* __restrict__ ckv,
                                  float* __restrict__ pks, float* __restrict__ pkv) {
    int c = blockIdx.x * blockDim.x + threadIdx.x;
    int b = blockIdx.y;
    float d = sigmoidf_(dp[c >> 7]);
    float dC = expf((float)CLEN * logf(d));
    float sks = 0.0f, skv = 0.0f;
    for (int j = 0; j < NCHUNK; j++) {
        int idx = (b * NCHUNK + j) * HID + c;
        pks[idx] = sks;
        pkv[idx] = skv;
        sks = dC * sks + cks[idx];
        skv = dC * skv + ckv[idx];
    }
}

// ---------------- scan pass C: add carry * d^(i+1) ------------------------
__global__ void scan_fix_kernel(const float* __restrict__ dp,
                                const float* __restrict__ pks, const float* __restrict__ pkv,
                                float* __restrict__ rks, float* __restrict__ rkv) {
    size_t idx = (size_t)blockIdx.x * blockDim.x + threadIdx.x;   // over M*HID
    int c = (int)(idx & (HID - 1));
    int t = (int)((idx >> 10) & (TT - 1));
    int b = (int)(idx >> 21);
    int i = t & (CLEN - 1);
    int j = t >> 7;
    float d = sigmoidf_(dp[c >> 7]);
    float pw = expf((float)(i + 1) * logf(d));
    int pidx = (b * NCHUNK + j) * HID + c;
    rks[idx] += pks[pidx] * pw;
    rkv[idx] += pkv[pidx] * pw;
}

// ---------------- den + o: warp per (row, head) ---------------------------
__global__ void attn_o_kernel(const float* __restrict__ qkv,
                              const float* __restrict__ rks, const float* __restrict__ rkv,
                              float* __restrict__ o) {
    int gw = (blockIdx.x * blockDim.x + threadIdx.x) >> 5;
    int lane = threadIdx.x & 31;
    int row = gw >> 3;
    int hh = gw & 7;
    size_t qbase = (size_t)row * 3072 + hh * HD;
    size_t rbase = (size_t)row * HID  + hh * HD;
    float qv[4], s = 0.0f;
    #pragma unroll
    for (int u = 0; u < 4; u++) {
        int dpos = lane + u * 32;
        qv[u] = qkv[qbase + dpos];
        s += qv[u] * rks[rbase + dpos];
    }
    #pragma unroll
    for (int k = 16; k; k >>= 1) s += __shfl_xor_sync(0xFFFFFFFFu, s, k);
    float inv = 1.0f / fmaxf(s, 1e-6f);
    #pragma unroll
    for (int u = 0; u < 4; u++) {
        int dpos = lane + u * 32;
        o[rbase + dpos] = qv[u] * rkv[rbase + dpos] * inv;
    }
}

// ---------------- out-gate mix: o2 = g*o + (1-g)*v ------------------------
__global__ void outgate_mix_kernel(const float* __restrict__ glin, const float* __restrict__ gb,
                                   const float* __restrict__ o, const float* __restrict__ qkv,
                                   float* __restrict__ o2) {
    size_t idx = (size_t)blockIdx.x * blockDim.x + threadIdx.x;   // over M*HID
    int c = (int)(idx & (HID - 1));
    size_t row = idx >> 10;
    float g = sigmoidf_(glin[idx] + gb[c]);
    float v = qkv[row * 3072 + 2048 + c];
    o2[idx] = g * o[idx] + (1.0f - g) * v;
}

// ---------------- gate-mix residual: x1 = x + s*local + (1-s)*attn --------
__global__ void gmix_residual_kernel(const float* __restrict__ x, const float* __restrict__ glin,
                                     const float* __restrict__ local, const float* __restrict__ attn,
                                     float* __restrict__ x1) {
    size_t idx = (size_t)blockIdx.x * blockDim.x + threadIdx.x;
    float s = sigmoidf_(glin[idx]);
    x1[idx] = x[idx] + s * local[idx] + (1.0f - s) * attn[idx];
}

// ---------------- swiglu: a = silu(a)*b -----------------------------------
__global__ void swiglu_kernel(float* __restrict__ a, const float* __restrict__ b) {
    size_t idx = (size_t)blockIdx.x * blockDim.x + threadIdx.x;   // over M*INTER
    a[idx] = siluf_(a[idx]) * b[idx];
}

// ---------------- final residual ------------------------------------------
__global__ void add_kernel(const float* __restrict__ a, const float* __restrict__ b,
                           float* __restrict__ o) {
    size_t idx = (size_t)blockIdx.x * blockDim.x + threadIdx.x;
    o[idx] = a[idx] + b[idx];
}

// ---------------- host side ------------------------------------------------
static inline void run_gemm(const float* A, int ldA, const float* W, int ldW,
                            float* C, int ldC, int M, int N, int K, bool acc) {
    dim3 grid(N / 128, M / 128);
    if (acc) sgemm_kernel<true><<<grid, 256>>>(A, ldA, W, ldW, C, ldC, K);
    else     sgemm_kernel<false><<<grid, 256>>>(A, ldA, W, ldW, C, ldC, K);
}

extern "C" void kernel_launch(void* const* d_in, const int* in_sizes, int n_in,
                              void* d_out, int out_size) {
    const float* x           = (const float*)d_in[0];
    const float* qkv_w       = (const float*)d_in[1];
    const float* out_proj_w  = (const float*)d_in[2];
    const float* out_gate_w  = (const float*)d_in[3];
    const float* out_gate_b  = (const float*)d_in[4];
    const float* decay_param = (const float*)d_in[5];
    const float* conv_w      = (const float*)d_in[6];
    const float* conv_b      = (const float*)d_in[7];
    const float* pw_w        = (const float*)d_in[8];
    const float* gate_w      = (const float*)d_in[9];
    const float* w1          = (const float*)d_in[10];
    const float* w2          = (const float*)d_in[11];
    const float* w3          = (const float*)d_in[12];
    const float* norm1_w     = (const float*)d_in[13];
    const float* norm2_w     = (const float*)d_in[14];
    float* out = (float*)d_out;

    float* S = nullptr;
    cudaGetSymbolAddress((void**)&S, g_scratch);

    float* g_h    = S + OFF_H;
    float* g_qkv  = S + OFF_QKV;
    float* g_conv = S + OFF_CONV;
    float* g_loc  = S + OFF_LOCAL;
    float* g_rks  = S + OFF_RKS;
    float* g_rkv  = S + OFF_RKV;
    float* g_o    = S + OFF_O;
    float* g_tmp  = S + OFF_TMP;
    float* g_o2   = S + OFF_O2;
    float* g_attn = S + OFF_ATTN;
    float* g_x1   = S + OFF_X1;
    float* g_h2   = S + OFF_H2;
    float* g_ffa  = S + OFF_FFA;
    float* g_ffb  = S + OFF_FFB;
    float* g_ffn  = S + OFF_FFN;
    float* g_cks  = S + OFF_CKS;
    float* g_ckv  = S + OFF_CKV;
    float* g_pks  = S + OFF_PKS;
    float* g_pkv  = S + OFF_PKV;

    const int NEH = 256;                       // elementwise block size
    const int GMH = (int)(SZ_MH / NEH);        // grid for M*HID
    const int GMI = (int)(SZ_MI / NEH);        // grid for M*INTER

    // 1. h = rmsnorm(x, norm1_w)
    rmsnorm_kernel<<<MROWS, 256>>>(x, norm1_w, g_h);

    // 2. qkv = h @ qkv_w^T   [8192,3072]
    run_gemm(g_h, HID, qkv_w, HID, g_qkv, 3 * HID, MROWS, 3 * HID, HID, false);

    // 3. conv branch: silu(depthwise conv + bias), then pointwise
    conv_silu_kernel<<<GMH, NEH>>>(g_h, conv_w, conv_b, g_conv);
    run_gemm(g_conv, HID, pw_w, HID, g_loc, HID, MROWS, HID, HID, false);

    // 4. elu+1 on q,k (in place)
    eluqk_kernel<<<(int)((size_t)MROWS * 2048 / NEH), NEH>>>(g_qkv);

    // 5. decayed scans (chunked)
    {
        dim3 gA(HID / 256, NCHUNK, BB);
        scan_chunk_kernel<<<gA, 256>>>(g_qkv, decay_param, g_rks, g_rkv, g_cks, g_ckv);
        dim3 gB(HID / 256, BB);
        scan_carry_kernel<<<gB, 256>>>(decay_param, g_cks, g_ckv, g_pks, g_pkv);
        scan_fix_kernel<<<GMH, NEH>>>(decay_param, g_pks, g_pkv, g_rks, g_rkv);
    }

    // 6. o = q * running_kv / max(sum(q*running_ks), 1e-6)
    attn_o_kernel<<<MROWS * NH * 32 / 256, 256>>>(g_qkv, g_rks, g_rkv, g_o);

    // 7. out gate: g = sigmoid(o @ W^T + b); o2 = g*o + (1-g)*v
    run_gemm(g_o, HID, out_gate_w, HID, g_tmp, HID, MROWS, HID, HID, false);
    outgate_mix_kernel<<<GMH, NEH>>>(g_tmp, out_gate_b, g_o, g_qkv, g_o2);

    // 8. attn = o2 @ out_proj^T
    run_gemm(g_o2, HID, out_proj_w, HID, g_attn, HID, MROWS, HID, HID, false);

    // 9. gmix = sigmoid([local|attn] @ gate_w^T)  (split-K over the concat)
    run_gemm(g_loc,  HID, gate_w,        2 * HID, g_tmp, HID, MROWS, HID, HID, false);
    run_gemm(g_attn, HID, gate_w + HID,  2 * HID, g_tmp, HID, MROWS, HID, HID, true);
    gmix_residual_kernel<<<GMH, NEH>>>(x, g_tmp, g_loc, g_attn, g_x1);

    // 10. FFN
    rmsnorm_kernel<<<MROWS, 256>>>(g_x1, norm2_w, g_h2);
    run_gemm(g_h2, HID, w1, HID, g_ffa, INTER, MROWS, INTER, HID, false);
    run_gemm(g_h2, HID, w2, HID, g_ffb, INTER, MROWS, INTER, HID, false);
    swiglu_kernel<<<GMI, NEH>>>(g_ffa, g_ffb);
    run_gemm(g_ffa, INTER, w3, INTER, g_ffn, HID, MROWS, HID, INTER, false);

    // 11. out = x1 + ffn
    add_kernel<<<GMH, NEH>>>(g_x1, g_ffn, out);
}

// round 2
// speedup vs baseline: 2.9452x; 2.9452x over previous
#include <cuda_runtime.h>
#include <math.h>

// Problem constants
#define BB      4
#define TT      2048
#define HID     1024
#define NH      8
#define HD      128
#define KS      4
#define INTER   2816
#define MROWS   (BB * TT)            // 8192
#define NCHUNK  16                   // T / 128
#define CLEN    128

// ---------------- scratch (single __device__ array, offsets in floats) ----
static const size_t SZ_MH = (size_t)MROWS * HID;      // 8388608
static const size_t SZ_MI = (size_t)MROWS * INTER;    // 23068672

static const size_t OFF_H     = 0;
static const size_t OFF_QKV   = OFF_H     + SZ_MH;        // 3*SZ_MH
static const size_t OFF_CONV  = OFF_QKV   + 3 * SZ_MH;
static const size_t OFF_LOCAL = OFF_CONV  + SZ_MH;
static const size_t OFF_RKS   = OFF_LOCAL + SZ_MH;
static const size_t OFF_RKV   = OFF_RKS   + SZ_MH;
static const size_t OFF_O     = OFF_RKV   + SZ_MH;
static const size_t OFF_TMP   = OFF_O     + SZ_MH;
static const size_t OFF_O2    = OFF_TMP   + SZ_MH;
static const size_t OFF_ATTN  = OFF_O2    + SZ_MH;
static const size_t OFF_X1    = OFF_ATTN  + SZ_MH;
static const size_t OFF_H2    = OFF_X1    + SZ_MH;
static const size_t OFF_FFA   = OFF_H2    + SZ_MH;
static const size_t OFF_FFB   = OFF_FFA   + SZ_MI;
static const size_t OFF_FFN   = OFF_FFB   + SZ_MI;
static const size_t OFF_CKS   = OFF_FFN   + SZ_MH;        // carries: B*NCHUNK*HID
static const size_t OFF_CKV   = OFF_CKS   + 65536;
static const size_t OFF_PKS   = OFF_CKV   + 65536;
static const size_t OFF_PKV   = OFF_PKS   + 65536;
static const size_t SCRATCH_FLOATS = OFF_PKV + 65536;

__device__ float g_scratch[SCRATCH_FLOATS];

// ---------------- helpers ----------------
__device__ __forceinline__ float sigmoidf_(float x) { return 1.0f / (1.0f + expf(-x)); }
__device__ __forceinline__ float siluf_(float x)    { return x / (1.0f + expf(-x)); }

__device__ __forceinline__ unsigned f2tf(float f) {
    unsigned u; asm("cvt.rna.tf32.f32 %0, %1;" : "=r"(u) : "f"(f)); return u;
}

__device__ __forceinline__ void mma_tf32(float* c, const unsigned* a, const unsigned* b) {
    asm volatile("mma.sync.aligned.m16n8k8.row.col.f32.tf32.tf32.f32 "
        "{%0,%1,%2,%3}, {%4,%5,%6,%7}, {%8,%9}, {%0,%1,%2,%3};"
        : "+f"(c[0]), "+f"(c[1]), "+f"(c[2]), "+f"(c[3])
        : "r"(a[0]), "r"(a[1]), "r"(a[2]), "r"(a[3]), "r"(b[0]), "r"(b[1]));
}

// ---------------- rmsnorm: one block (256 thr) per row of 1024 ------------
__global__ void rmsnorm_kernel(const float* __restrict__ x, const float* __restrict__ w,
                               float* __restrict__ o) {
    int row = blockIdx.x;
    size_t base = (size_t)row * HID;
    float4 v = ((const float4*)(x + base))[threadIdx.x];
    float ss = v.x * v.x + v.y * v.y + v.z * v.z + v.w * v.w;
    __shared__ float sred[8];
    int lane = threadIdx.x & 31, wid = threadIdx.x >> 5;
    #pragma unroll
    for (int k = 16; k; k >>= 1) ss += __shfl_xor_sync(0xFFFFFFFFu, ss, k);
    if (lane == 0) sred[wid] = ss;
    __syncthreads();
    if (wid == 0) {
        float t = (lane < 8) ? sred[lane] : 0.0f;
        #pragma unroll
        for (int k = 4; k; k >>= 1) t += __shfl_xor_sync(0xFFFFFFFFu, t, k);
        if (lane == 0) sred[0] = t;
    }
    __syncthreads();
    float scale = rsqrtf(sred[0] * (1.0f / (float)HID) + 1e-6f);
    float4 wv = ((const float4*)w)[threadIdx.x];
    float4 r = make_float4(v.x * scale * wv.x, v.y * scale * wv.y,
                           v.z * scale * wv.z, v.w * scale * wv.w);
    ((float4*)(o + base))[threadIdx.x] = r;
}

// ---------------- TF32 tensor-core GEMM -----------------------------------
// C[M,N](ldC) = A[M,K](ldA) @ W[N,K](ldW)^T ; 128x128x32 tile, 8 warps,
// each warp 64x32 via 4x4 m16n8k8 tiles. Smem row pitch 36 floats (conflict-
// free fragment LDS; 144B row pitch is 16B aligned for cp.async).
#define SPITCH 36
#define SBUF   (128 * SPITCH)   // floats per stage per operand

__device__ __forceinline__ void tile_load(float* s, const float* g, int ld, int k0, int tid) {
    #pragma unroll
    for (int i = 0; i < 4; i++) {
        int idx = tid + i * 256;
        int row = idx >> 3;
        int c4  = (idx & 7) * 4;
        unsigned saddr = (unsigned)__cvta_generic_to_shared(s + row * SPITCH + c4);
        const float* gp = g + (size_t)row * ld + k0 + c4;
        asm volatile("cp.async.cg.shared.global [%0], [%1], 16;" :: "r"(saddr), "l"(gp));
    }
}

template <bool ACC>
__global__ __launch_bounds__(256, 2)
void tgemm_kernel(const float* __restrict__ A, int ldA,
                  const float* __restrict__ W, int ldW,
                  float* __restrict__ C, int ldC, int K) {
    extern __shared__ float smem[];
    float* AsB = smem;             // [2][SBUF]
    float* WsB = smem + 2 * SBUF;  // [2][SBUF]
    int tid = threadIdx.x;
    int wid = tid >> 5, lane = tid & 31;
    int warp_m = wid & 1, warp_n = wid >> 1;
    int m0 = blockIdx.y * 128, n0 = blockIdx.x * 128;
    const float* Ag = A + (size_t)m0 * ldA;
    const float* Wg = W + (size_t)n0 * ldW;
    int qr = lane >> 2, qc = lane & 3;

    float acc[4][4][4];
    #pragma unroll
    for (int mt = 0; mt < 4; mt++)
        #pragma unroll
        for (int nt = 0; nt < 4; nt++)
            #pragma unroll
            for (int i = 0; i < 4; i++) acc[mt][nt][i] = 0.0f;

    int KT = K / 32;
    tile_load(AsB, Ag, ldA, 0, tid);
    tile_load(WsB, Wg, ldW, 0, tid);
    asm volatile("cp.async.commit_group;");

    for (int kt = 0; kt < KT; kt++) {
        int cur = kt & 1;
        if (kt + 1 < KT) {
            tile_load(AsB + (cur ^ 1) * SBUF, Ag, ldA, (kt + 1) * 32, tid);
            tile_load(WsB + (cur ^ 1) * SBUF, Wg, ldW, (kt + 1) * 32, tid);
            asm volatile("cp.async.commit_group;");
            asm volatile("cp.async.wait_group 1;");
        } else {
            asm volatile("cp.async.wait_group 0;");
        }
        __syncthreads();
        const float* Ab = AsB + cur * SBUF;
        const float* Wb = WsB + cur * SBUF;
        #pragma unroll
        for (int ks = 0; ks < 4; ks++) {
            int k0 = ks * 8;
            unsigned af[4][4], bf[4][2];
            #pragma unroll
            for (int mt = 0; mt < 4; mt++) {
                int r = warp_m * 64 + mt * 16 + qr;
                af[mt][0] = f2tf(Ab[r * SPITCH + k0 + qc]);
                af[mt][1] = f2tf(Ab[(r + 8) * SPITCH + k0 + qc]);
                af[mt][2] = f2tf(Ab[r * SPITCH + k0 + qc + 4]);
                af[mt][3] = f2tf(Ab[(r + 8) * SPITCH + k0 + qc + 4]);
            }
            #pragma unroll
            for (int nt = 0; nt < 4; nt++) {
                int cc = warp_n * 32 + nt * 8 + qr;
                bf[nt][0] = f2tf(Wb[cc * SPITCH + k0 + qc]);
                bf[nt][1] = f2tf(Wb[cc * SPITCH + k0 + qc + 4]);
            }
            #pragma unroll
            for (int mt = 0; mt < 4; mt++)
                #pragma unroll
                for (int nt = 0; nt < 4; nt++)
                    mma_tf32(acc[mt][nt], af[mt], bf[nt]);
        }
        __syncthreads();
    }

    #pragma unroll
    for (int mt = 0; mt < 4; mt++)
        #pragma unroll
        for (int nt = 0; nt < 4; nt++) {
            int row = m0 + warp_m * 64 + mt * 16 + qr;
            int col = n0 + warp_n * 32 + nt * 8 + qc * 2;
            float* p0 = C + (size_t)row * ldC + col;
            float* p1 = C + (size_t)(row + 8) * ldC + col;
            float2 r0 = make_float2(acc[mt][nt][0], acc[mt][nt][1]);
            float2 r1 = make_float2(acc[mt][nt][2], acc[mt][nt][3]);
            if (ACC) {
                float2 o0 = *(float2*)p0, o1 = *(float2*)p1;
                r0.x += o0.x; r0.y += o0.y; r1.x += o1.x; r1.y += o1.y;
            }
            *(float2*)p0 = r0;
            *(float2*)p1 = r1;
        }
}

// ---------------- depthwise causal conv (KS=4) + bias + silu --------------
__global__ void conv_silu_kernel(const float* __restrict__ h, const float* __restrict__ cw,
                                 const float* __restrict__ cb, float* __restrict__ o) {
    size_t idx = (size_t)blockIdx.x * blockDim.x + threadIdx.x;   // over M*HID
    int c = idx & (HID - 1);
    int t = (int)((idx >> 10) & (TT - 1));
    int b = (int)(idx >> 21);
    float acc = cb[c];
    #pragma unroll
    for (int j = 0; j < KS; j++) {
        int tt = t + j - (KS - 1);
        if (tt >= 0) acc += h[((size_t)(b * TT + tt)) * HID + c] * cw[c * KS + j];
    }
    o[idx] = siluf_(acc);
}

// ---------------- elu(x)+1 applied in place to q,k cols of qkv ------------
__global__ void eluqk_kernel(float* __restrict__ qkv) {
    size_t idx = (size_t)blockIdx.x * blockDim.x + threadIdx.x;   // over M*2048
    size_t row = idx >> 11;
    int col = (int)(idx & 2047);
    float* p = qkv + row * 3072 + col;
    float v = *p;
    *p = (v > 0.0f) ? (v + 1.0f) : expf(v);
}

// ---------------- scan pass A: per-chunk local recurrence -----------------
__global__ void scan_chunk_kernel(const float* __restrict__ qkv, const float* __restrict__ dp,
                                  float* __restrict__ rks, float* __restrict__ rkv,
                                  float* __restrict__ cks, float* __restrict__ ckv) {
    int c = blockIdx.x * blockDim.x + threadIdx.x;   // 0..1023
    int j = blockIdx.y;                               // chunk
    int b = blockIdx.z;
    float d = sigmoidf_(dp[c >> 7]);
    float sks = 0.0f, skv = 0.0f;
    size_t base  = ((size_t)(b * TT + j * CLEN)) * 3072 + c;
    size_t obase = ((size_t)(b * TT + j * CLEN)) * HID + c;
    for (int i = 0; i < CLEN; i++) {
        float kk = qkv[base + 1024];
        float vv = qkv[base + 2048];
        sks = d * sks + kk;
        skv = d * skv + kk * vv;
        rks[obase] = sks;
        rkv[obase] = skv;
        base += 3072; obase += HID;
    }
    cks[(b * NCHUNK + j) * HID + c] = sks;
    ckv[(b * NCHUNK + j) * HID + c] = skv;
}

// ---------------- scan pass B: carry propagation across 16 chunks ---------
__global__ void scan_carry_kernel(const float* __restrict__ dp,
                                  const float* __restrict__ cks, const float* __restrict__ ckv,
                                  float* __restrict__ pks, float* __restrict__ pkv) {
    int c = blockIdx.x * blockDim.x + threadIdx.x;
    int b = blockIdx.y;
    float d = sigmoidf_(dp[c >> 7]);
    float dC = expf((float)CLEN * logf(d));
    float sks = 0.0f, skv = 0.0f;
    for (int j = 0; j < NCHUNK; j++) {
        int idx = (b * NCHUNK + j) * HID + c;
        pks[idx] = sks;
        pkv[idx] = skv;
        sks = dC * sks + cks[idx];
        skv = dC * skv + ckv[idx];
    }
}

// ---------------- scan pass C: add carry * d^(i+1) ------------------------
__global__ void scan_fix_kernel(const float* __restrict__ dp,
                                const float* __restrict__ pks, const float* __restrict__ pkv,
                                float* __restrict__ rks, float* __restrict__ rkv) {
    size_t idx = (size_t)blockIdx.x * blockDim.x + threadIdx.x;   // over M*HID
    int c = (int)(idx & (HID - 1));
    int t = (int)((idx >> 10) & (TT - 1));
    int b = (int)(idx >> 21);
    int i = t & (CLEN - 1);
    int j = t >> 7;
    float d = sigmoidf_(dp[c >> 7]);
    float pw = expf((float)(i + 1) * logf(d));
    int pidx = (b * NCHUNK + j) * HID + c;
    rks[idx] += pks[pidx] * pw;
    rkv[idx] += pkv[pidx] * pw;
}

// ---------------- den + o: warp per (row, head) ---------------------------
__global__ void attn_o_kernel(const float* __restrict__ qkv,
                              const float* __restrict__ rks, const float* __restrict__ rkv,
                              float* __restrict__ o) {
    int gw = (blockIdx.x * blockDim.x + threadIdx.x) >> 5;
    int lane = threadIdx.x & 31;
    int row = gw >> 3;
    int hh = gw & 7;
    size_t qbase = (size_t)row * 3072 + hh * HD;
    size_t rbase = (size_t)row * HID  + hh * HD;
    float qv[4], s = 0.0f;
    #pragma unroll
    for (int u = 0; u < 4; u++) {
        int dpos = lane + u * 32;
        qv[u] = qkv[qbase + dpos];
        s += qv[u] * rks[rbase + dpos];
    }
    #pragma unroll
    for (int k = 16; k; k >>= 1) s += __shfl_xor_sync(0xFFFFFFFFu, s, k);
    float inv = 1.0f / fmaxf(s, 1e-6f);
    #pragma unroll
    for (int u = 0; u < 4; u++) {
        int dpos = lane + u * 32;
        o[rbase + dpos] = qv[u] * rkv[rbase + dpos] * inv;
    }
}

// ---------------- out-gate mix: o2 = g*o + (1-g)*v ------------------------
__global__ void outgate_mix_kernel(const float* __restrict__ glin, const float* __restrict__ gb,
                                   const float* __restrict__ o, const float* __restrict__ qkv,
                                   float* __restrict__ o2) {
    size_t idx = (size_t)blockIdx.x * blockDim.x + threadIdx.x;   // over M*HID
    int c = (int)(idx & (HID - 1));
    size_t row = idx >> 10;
    float g = sigmoidf_(glin[idx] + gb[c]);
    float v = qkv[row * 3072 + 2048 + c];
    o2[idx] = g * o[idx] + (1.0f - g) * v;
}

// ---------------- gate-mix residual: x1 = x + s*local + (1-s)*attn --------
__global__ void gmix_residual_kernel(const float* __restrict__ x, const float* __restrict__ glin,
                                     const float* __restrict__ local, const float* __restrict__ attn,
                                     float* __restrict__ x1) {
    size_t idx = (size_t)blockIdx.x * blockDim.x + threadIdx.x;
    float s = sigmoidf_(glin[idx]);
    x1[idx] = x[idx] + s * local[idx] + (1.0f - s) * attn[idx];
}

// ---------------- swiglu: a = silu(a)*b -----------------------------------
__global__ void swiglu_kernel(float* __restrict__ a, const float* __restrict__ b) {
    size_t idx = (size_t)blockIdx.x * blockDim.x + threadIdx.x;   // over M*INTER
    a[idx] = siluf_(a[idx]) * b[idx];
}

// ---------------- final residual ------------------------------------------
__global__ void add_kernel(const float* __restrict__ a, const float* __restrict__ b,
                           float* __restrict__ o) {
    size_t idx = (size_t)blockIdx.x * blockDim.x + threadIdx.x;
    o[idx] = a[idx] + b[idx];
}

// ---------------- host side ------------------------------------------------
#define TGEMM_SMEM (4 * SBUF * sizeof(float))   // 73728 bytes

static inline void run_gemm(const float* A, int ldA, const float* W, int ldW,
                            float* C, int ldC, int M, int N, int K, bool acc) {
    dim3 grid(N / 128, M / 128);
    if (acc) tgemm_kernel<true><<<grid, 256, TGEMM_SMEM>>>(A, ldA, W, ldW, C, ldC, K);
    else     tgemm_kernel<false><<<grid, 256, TGEMM_SMEM>>>(A, ldA, W, ldW, C, ldC, K);
}

extern "C" void kernel_launch(void* const* d_in, const int* in_sizes, int n_in,
                              void* d_out, int out_size) {
    const float* x           = (const float*)d_in[0];
    const float* qkv_w       = (const float*)d_in[1];
    const float* out_proj_w  = (const float*)d_in[2];
    const float* out_gate_w  = (const float*)d_in[3];
    const float* out_gate_b  = (const float*)d_in[4];
    const float* decay_param = (const float*)d_in[5];
    const float* conv_w      = (const float*)d_in[6];
    const float* conv_b      = (const float*)d_in[7];
    const float* pw_w        = (const float*)d_in[8];
    const float* gate_w      = (const float*)d_in[9];
    const float* w1          = (const float*)d_in[10];
    const float* w2          = (const float*)d_in[11];
    const float* w3          = (const float*)d_in[12];
    const float* norm1_w     = (const float*)d_in[13];
    const float* norm2_w     = (const float*)d_in[14];
    float* out = (float*)d_out;

    static int smem_set = 0;
    if (!smem_set) {
        cudaFuncSetAttribute(tgemm_kernel<false>,
                             cudaFuncAttributeMaxDynamicSharedMemorySize, (int)TGEMM_SMEM);
        cudaFuncSetAttribute(tgemm_kernel<true>,
                             cudaFuncAttributeMaxDynamicSharedMemorySize, (int)TGEMM_SMEM);
        smem_set = 1;
    }

    float* S = nullptr;
    cudaGetSymbolAddress((void**)&S, g_scratch);

    float* g_h    = S + OFF_H;
    float* g_qkv  = S + OFF_QKV;
    float* g_conv = S + OFF_CONV;
    float* g_loc  = S + OFF_LOCAL;
    float* g_rks  = S + OFF_RKS;
    float* g_rkv  = S + OFF_RKV;
    float* g_o    = S + OFF_O;
    float* g_tmp  = S + OFF_TMP;
    float* g_o2   = S + OFF_O2;
    float* g_attn = S + OFF_ATTN;
    float* g_x1   = S + OFF_X1;
    float* g_h2   = S + OFF_H2;
    float* g_ffa  = S + OFF_FFA;
    float* g_ffb  = S + OFF_FFB;
    float* g_ffn  = S + OFF_FFN;
    float* g_cks  = S + OFF_CKS;
    float* g_ckv  = S + OFF_CKV;
    float* g_pks  = S + OFF_PKS;
    float* g_pkv  = S + OFF_PKV;

    const int NEH = 256;
    const int GMH = (int)(SZ_MH / NEH);
    const int GMI = (int)(SZ_MI / NEH);

    // 1. h = rmsnorm(x, norm1_w)
    rmsnorm_kernel<<<MROWS, 256>>>(x, norm1_w, g_h);

    // 2. qkv = h @ qkv_w^T   [8192,3072]
    run_gemm(g_h, HID, qkv_w, HID, g_qkv, 3 * HID, MROWS, 3 * HID, HID, false);

    // 3. conv branch: silu(depthwise conv + bias), then pointwise
    conv_silu_kernel<<<GMH, NEH>>>(g_h, conv_w, conv_b, g_conv);
    run_gemm(g_conv, HID, pw_w, HID, g_loc, HID, MROWS, HID, HID, false);

    // 4. elu+1 on q,k (in place)
    eluqk_kernel<<<(int)((size_t)MROWS * 2048 / NEH), NEH>>>(g_qkv);

    // 5. decayed scans (chunked)
    {
        dim3 gA(HID / 256, NCHUNK, BB);
        scan_chunk_kernel<<<gA, 256>>>(g_qkv, decay_param, g_rks, g_rkv, g_cks, g_ckv);
        dim3 gB(HID / 256, BB);
        scan_carry_kernel<<<gB, 256>>>(decay_param, g_cks, g_ckv, g_pks, g_pkv);
        scan_fix_kernel<<<GMH, NEH>>>(decay_param, g_pks, g_pkv, g_rks, g_rkv);
    }

    // 6. o = q * running_kv / max(sum(q*running_ks), 1e-6)
    attn_o_kernel<<<MROWS * NH * 32 / 256, 256>>>(g_qkv, g_rks, g_rkv, g_o);

    // 7. out gate: g = sigmoid(o @ W^T + b); o2 = g*o + (1-g)*v
    run_gemm(g_o, HID, out_gate_w, HID, g_tmp, HID, MROWS, HID, HID, false);
    outgate_mix_kernel<<<GMH, NEH>>>(g_tmp, out_gate_b, g_o, g_qkv, g_o2);

    // 8. attn = o2 @ out_proj^T
    run_gemm(g_o2, HID, out_proj_w, HID, g_attn, HID, MROWS, HID, HID, false);

    // 9. gmix = sigmoid([local|attn] @ gate_w^T)  (split-K over the concat)
    run_gemm(g_loc,  HID, gate_w,        2 * HID, g_tmp, HID, MROWS, HID, HID, false);
    run_gemm(g_attn, HID, gate_w + HID,  2 * HID, g_tmp, HID, MROWS, HID, HID, true);
    gmix_residual_kernel<<<GMH, NEH>>>(x, g_tmp, g_loc, g_attn, g_x1);

    // 10. FFN
    rmsnorm_kernel<<<MROWS, 256>>>(g_x1, norm2_w, g_h2);
    run_gemm(g_h2, HID, w1, HID, g_ffa, INTER, MROWS, INTER, HID, false);
    run_gemm(g_h2, HID, w2, HID, g_ffb, INTER, MROWS, INTER, HID, false);
    swiglu_kernel<<<GMI, NEH>>>(g_ffa, g_ffb);
    run_gemm(g_ffa, INTER, w3, INTER, g_ffn, HID, MROWS, HID, INTER, false);

    // 11. out = x1 + ffn
    add_kernel<<<GMH, NEH>>>(g_x1, g_ffn, out);
}

// round 4
// speedup vs baseline: 3.1489x; 1.0692x over previous
#include <cuda_runtime.h>
#include <math.h>
#include <stdint.h>

// Problem constants
#define BB      4
#define TT      2048
#define HID     1024
#define NH      8
#define HD      128
#define KS      4
#define INTER   2816
#define MROWS   (BB * TT)            // 8192
#define NCHUNK  16                   // T / 128
#define CLEN    128

// ---------------- scratch (single __device__ array, offsets in floats) ----
static const size_t SZ_MH = (size_t)MROWS * HID;      // 8388608
static const size_t SZ_MI = (size_t)MROWS * INTER;    // 23068672

static const size_t OFF_H     = 0;
static const size_t OFF_QKV   = OFF_H     + SZ_MH;
static const size_t OFF_CONV  = OFF_QKV   + 3 * SZ_MH;
static const size_t OFF_LOCAL = OFF_CONV  + SZ_MH;
static const size_t OFF_RKS   = OFF_LOCAL + SZ_MH;
static const size_t OFF_RKV   = OFF_RKS   + SZ_MH;
static const size_t OFF_O     = OFF_RKV   + SZ_MH;
static const size_t OFF_TMP   = OFF_O     + SZ_MH;
static const size_t OFF_O2    = OFF_TMP   + SZ_MH;
static const size_t OFF_ATTN  = OFF_O2    + SZ_MH;
static const size_t OFF_X1    = OFF_ATTN  + SZ_MH;
static const size_t OFF_H2    = OFF_X1    + SZ_MH;
static const size_t OFF_FFA   = OFF_H2    + SZ_MH;
static const size_t OFF_FFB   = OFF_FFA   + SZ_MI;
static const size_t OFF_FFN   = OFF_FFB   + SZ_MI;
static const size_t OFF_CKS   = OFF_FFN   + SZ_MH;
static const size_t OFF_CKV   = OFF_CKS   + 65536;
static const size_t OFF_PKS   = OFF_CKV   + 65536;
static const size_t OFF_PKV   = OFF_PKS   + 65536;
// tf32-rounded weight copies
static const size_t OFF_WQKV  = OFF_PKV   + 65536;
static const size_t OFF_WOP   = OFF_WQKV  + 3 * (size_t)HID * HID;
static const size_t OFF_WOG   = OFF_WOP   + (size_t)HID * HID;
static const size_t OFF_WPW   = OFF_WOG   + (size_t)HID * HID;
static const size_t OFF_WGT   = OFF_WPW   + (size_t)HID * HID;
static const size_t OFF_WW1   = OFF_WGT   + 2 * (size_t)HID * HID;
static const size_t OFF_WW2   = OFF_WW1   + (size_t)INTER * HID;
static const size_t OFF_WW3   = OFF_WW2   + (size_t)INTER * HID;
static const size_t SCRATCH_FLOATS = OFF_WW3 + (size_t)INTER * HID;

__device__ float g_scratch[SCRATCH_FLOATS];

// ---------------- helpers ----------------
__device__ __forceinline__ float sigmoidf_(float x) { return 1.0f / (1.0f + expf(-x)); }
__device__ __forceinline__ float siluf_(float x)    { return x / (1.0f + expf(-x)); }

__device__ __forceinline__ unsigned f2tf(float f) {
    unsigned u; asm("cvt.rna.tf32.f32 %0, %1;" : "=r"(u) : "f"(f)); return u;
}
__device__ __forceinline__ float tf32r(float f) { return __uint_as_float(f2tf(f)); }

__device__ __forceinline__ void mma_tf32(float* c, const unsigned* a, const unsigned* b) {
    asm volatile("mma.sync.aligned.m16n8k8.row.col.f32.tf32.tf32.f32 "
        "{%0,%1,%2,%3}, {%4,%5,%6,%7}, {%8,%9}, {%0,%1,%2,%3};"
        : "+f"(c[0]), "+f"(c[1]), "+f"(c[2]), "+f"(c[3])
        : "r"(a[0]), "r"(a[1]), "r"(a[2]), "r"(a[3]), "r"(b[0]), "r"(b[1]));
}

// ---------------- weight tf32 rounding ------------------------------------
__global__ void cvt_tf32_kernel(const float* __restrict__ s, float* __restrict__ d, int n) {
    int i = blockIdx.x * blockDim.x + threadIdx.x;
    if (i < n) d[i] = tf32r(s[i]);
}

// ---------------- rmsnorm (tf32-rounded output) ---------------------------
__global__ void rmsnorm_kernel(const float* __restrict__ x, const float* __restrict__ w,
                               float* __restrict__ o) {
    int row = blockIdx.x;
    size_t base = (size_t)row * HID;
    float4 v = ((const float4*)(x + base))[threadIdx.x];
    float ss = v.x * v.x + v.y * v.y + v.z * v.z + v.w * v.w;
    __shared__ float sred[8];
    int lane = threadIdx.x & 31, wid = threadIdx.x >> 5;
    #pragma unroll
    for (int k = 16; k; k >>= 1) ss += __shfl_xor_sync(0xFFFFFFFFu, ss, k);
    if (lane == 0) sred[wid] = ss;
    __syncthreads();
    if (wid == 0) {
        float t = (lane < 8) ? sred[lane] : 0.0f;
        #pragma unroll
        for (int k = 4; k; k >>= 1) t += __shfl_xor_sync(0xFFFFFFFFu, t, k);
        if (lane == 0) sred[0] = t;
    }
    __syncthreads();
    float scale = rsqrtf(sred[0] * (1.0f / (float)HID) + 1e-6f);
    float4 wv = ((const float4*)w)[threadIdx.x];
    float4 r = make_float4(tf32r(v.x * scale * wv.x), tf32r(v.y * scale * wv.y),
                           tf32r(v.z * scale * wv.z), tf32r(v.w * scale * wv.w));
    ((float4*)(o + base))[threadIdx.x] = r;
}

// ---------------- TF32 tensor-core GEMM (no in-loop CVT) -------------------
// C[M,N](ldC) = A[M,K](ldA) @ W[N,K](ldW)^T. Inputs MUST be pre-rounded to
// tf32 (rna). 128x128x32 tile, 8 warps, each warp 64x32 via 4x4 m16n8k8.
#define SPITCH 36
#define SBUF   (128 * SPITCH)

__device__ __forceinline__ void tile_load(float* s, const float* g, int ld, int k0, int tid) {
    #pragma unroll
    for (int i = 0; i < 4; i++) {
        int idx = tid + i * 256;
        int row = idx >> 3;
        int c4  = (idx & 7) * 4;
        unsigned saddr = (unsigned)__cvta_generic_to_shared(s + row * SPITCH + c4);
        const float* gp = g + (size_t)row * ld + k0 + c4;
        asm volatile("cp.async.cg.shared.global [%0], [%1], 16;" :: "r"(saddr), "l"(gp));
    }
}

template <bool ACC, bool ROUND>
__global__ __launch_bounds__(256, 2)
void tgemm_kernel(const float* __restrict__ A, int ldA,
                  const float* __restrict__ W, int ldW,
                  float* __restrict__ C, int ldC, int K) {
    extern __shared__ float smem[];
    float* AsB = smem;
    float* WsB = smem + 2 * SBUF;
    int tid = threadIdx.x;
    int wid = tid >> 5, lane = tid & 31;
    int warp_m = wid & 1, warp_n = wid >> 1;
    int m0 = blockIdx.y * 128, n0 = blockIdx.x * 128;
    const float* Ag = A + (size_t)m0 * ldA;
    const float* Wg = W + (size_t)n0 * ldW;
    int qr = lane >> 2, qc = lane & 3;

    float acc[4][4][4];
    #pragma unroll
    for (int mt = 0; mt < 4; mt++)
        #pragma unroll
        for (int nt = 0; nt < 4; nt++)
            #pragma unroll
            for (int i = 0; i < 4; i++) acc[mt][nt][i] = 0.0f;

    int KT = K / 32;
    tile_load(AsB, Ag, ldA, 0, tid);
    tile_load(WsB, Wg, ldW, 0, tid);
    asm volatile("cp.async.commit_group;");

    for (int kt = 0; kt < KT; kt++) {
        int cur = kt & 1;
        if (kt + 1 < KT) {
            tile_load(AsB + (cur ^ 1) * SBUF, Ag, ldA, (kt + 1) * 32, tid);
            tile_load(WsB + (cur ^ 1) * SBUF, Wg, ldW, (kt + 1) * 32, tid);
            asm volatile("cp.async.commit_group;");
            asm volatile("cp.async.wait_group 1;");
        } else {
            asm volatile("cp.async.wait_group 0;");
        }
        __syncthreads();
        const unsigned* Ab = (const unsigned*)(AsB + cur * SBUF);
        const unsigned* Wb = (const unsigned*)(WsB + cur * SBUF);
        #pragma unroll
        for (int ks = 0; ks < 4; ks++) {
            int k0 = ks * 8;
            unsigned af[4][4], bf[4][2];
            #pragma unroll
            for (int mt = 0; mt < 4; mt++) {
                int r = warp_m * 64 + mt * 16 + qr;
                af[mt][0] = Ab[r * SPITCH + k0 + qc];
                af[mt][1] = Ab[(r + 8) * SPITCH + k0 + qc];
                af[mt][2] = Ab[r * SPITCH + k0 + qc + 4];
                af[mt][3] = Ab[(r + 8) * SPITCH + k0 + qc + 4];
            }
            #pragma unroll
            for (int nt = 0; nt < 4; nt++) {
                int cc = warp_n * 32 + nt * 8 + qr;
                bf[nt][0] = Wb[cc * SPITCH + k0 + qc];
                bf[nt][1] = Wb[cc * SPITCH + k0 + qc + 4];
            }
            #pragma unroll
            for (int mt = 0; mt < 4; mt++)
                #pragma unroll
                for (int nt = 0; nt < 4; nt++)
                    mma_tf32(acc[mt][nt], af[mt], bf[nt]);
        }
        __syncthreads();
    }

    #pragma unroll
    for (int mt = 0; mt < 4; mt++)
        #pragma unroll
        for (int nt = 0; nt < 4; nt++) {
            int row = m0 + warp_m * 64 + mt * 16 + qr;
            int col = n0 + warp_n * 32 + nt * 8 + qc * 2;
            float* p0 = C + (size_t)row * ldC + col;
            float* p1 = C + (size_t)(row + 8) * ldC + col;
            float2 r0 = make_float2(acc[mt][nt][0], acc[mt][nt][1]);
            float2 r1 = make_float2(acc[mt][nt][2], acc[mt][nt][3]);
            if (ROUND) {
                r0.x = tf32r(r0.x); r0.y = tf32r(r0.y);
                r1.x = tf32r(r1.x); r1.y = tf32r(r1.y);
            }
            if (ACC) {
                float2 o0 = *(float2*)p0, o1 = *(float2*)p1;
                r0.x += o0.x; r0.y += o0.y; r1.x += o1.x; r1.y += o1.y;
            }
            *(float2*)p0 = r0;
            *(float2*)p1 = r1;
        }
}

// ---------------- depthwise causal conv (KS=4) + bias + silu --------------
__global__ void conv_silu_kernel(const float* __restrict__ h, const float* __restrict__ cw,
                                 const float* __restrict__ cb, float* __restrict__ o) {
    size_t idx = (size_t)blockIdx.x * blockDim.x + threadIdx.x;
    int c = idx & (HID - 1);
    int t = (int)((idx >> 10) & (TT - 1));
    int b = (int)(idx >> 21);
    float acc = cb[c];
    #pragma unroll
    for (int j = 0; j < KS; j++) {
        int tt = t + j - (KS - 1);
        if (tt >= 0) acc += h[((size_t)(b * TT + tt)) * HID + c] * cw[c * KS + j];
    }
    o[idx] = tf32r(siluf_(acc));
}

// ---------------- elu(x)+1 applied in place to q,k cols of qkv ------------
__global__ void eluqk_kernel(float* __restrict__ qkv) {
    size_t idx = (size_t)blockIdx.x * blockDim.x + threadIdx.x;
    size_t row = idx >> 11;
    int col = (int)(idx & 2047);
    float* p = qkv + row * 3072 + col;
    float v = *p;
    *p = (v > 0.0f) ? (v + 1.0f) : expf(v);
}

// ---------------- scan pass A ---------------------------------------------
__global__ void scan_chunk_kernel(const float* __restrict__ qkv, const float* __restrict__ dp,
                                  float* __restrict__ rks, float* __restrict__ rkv,
                                  float* __restrict__ cks, float* __restrict__ ckv) {
    int c = blockIdx.x * blockDim.x + threadIdx.x;
    int j = blockIdx.y;
    int b = blockIdx.z;
    float d = sigmoidf_(dp[c >> 7]);
    float sks = 0.0f, skv = 0.0f;
    size_t base  = ((size_t)(b * TT + j * CLEN)) * 3072 + c;
    size_t obase = ((size_t)(b * TT + j * CLEN)) * HID + c;
    for (int i = 0; i < CLEN; i++) {
        float kk = qkv[base + 1024];
        float vv = qkv[base + 2048];
        sks = d * sks + kk;
        skv = d * skv + kk * vv;
        rks[obase] = sks;
        rkv[obase] = skv;
        base += 3072; obase += HID;
    }
    cks[(b * NCHUNK + j) * HID + c] = sks;
    ckv[(b * NCHUNK + j) * HID + c] = skv;
}

// ---------------- scan pass B ---------------------------------------------
__global__ void scan_carry_kernel(const float* __restrict__ dp,
                                  const float* __restrict__ cks, const float* __restrict__ ckv,
                                  float* __restrict__ pks, float* __restrict__ pkv) {
    int c = blockIdx.x * blockDim.x + threadIdx.x;
    int b = blockIdx.y;
    float d = sigmoidf_(dp[c >> 7]);
    float dC = expf((float)CLEN * logf(d));
    float sks = 0.0f, skv = 0.0f;
    for (int j = 0; j < NCHUNK; j++) {
        int idx = (b * NCHUNK + j) * HID + c;
        pks[idx] = sks;
        pkv[idx] = skv;
        sks = dC * sks + cks[idx];
        skv = dC * skv + ckv[idx];
    }
}

// ---------------- scan pass C ---------------------------------------------
__global__ void scan_fix_kernel(const float* __restrict__ dp,
                                const float* __restrict__ pks, const float* __restrict__ pkv,
                                float* __restrict__ rks, float* __restrict__ rkv) {
    size_t idx = (size_t)blockIdx.x * blockDim.x + threadIdx.x;
    int c = (int)(idx & (HID - 1));
    int t = (int)((idx >> 10) & (TT - 1));
    int b = (int)(idx >> 21);
    int i = t & (CLEN - 1);
    int j = t >> 7;
    float d = sigmoidf_(dp[c >> 7]);
    float pw = expf((float)(i + 1) * logf(d));
    int pidx = (b * NCHUNK + j) * HID + c;
    rks[idx] += pks[pidx] * pw;
    rkv[idx] += pkv[pidx] * pw;
}

// ---------------- den + o (tf32-rounded output) ---------------------------
__global__ void attn_o_kernel(const float* __restrict__ qkv,
                              const float* __restrict__ rks, const float* __restrict__ rkv,
                              float* __restrict__ o) {
    int gw = (blockIdx.x * blockDim.x + threadIdx.x) >> 5;
    int lane = threadIdx.x & 31;
    int row = gw >> 3;
    int hh = gw & 7;
    size_t qbase = (size_t)row * 3072 + hh * HD;
    size_t rbase = (size_t)row * HID  + hh * HD;
    float qv[4], s = 0.0f;
    #pragma unroll
    for (int u = 0; u < 4; u++) {
        int dpos = lane + u * 32;
        qv[u] = qkv[qbase + dpos];
        s += qv[u] * rks[rbase + dpos];
    }
    #pragma unroll
    for (int k = 16; k; k >>= 1) s += __shfl_xor_sync(0xFFFFFFFFu, s, k);
    float inv = 1.0f / fmaxf(s, 1e-6f);
    #pragma unroll
    for (int u = 0; u < 4; u++) {
        int dpos = lane + u * 32;
        o[rbase + dpos] = tf32r(qv[u] * rkv[rbase + dpos] * inv);
    }
}

// ---------------- out-gate mix (tf32-rounded output) ----------------------
__global__ void outgate_mix_kernel(const float* __restrict__ glin, const float* __restrict__ gb,
                                   const float* __restrict__ o, const float* __restrict__ qkv,
                                   float* __restrict__ o2) {
    size_t idx = (size_t)blockIdx.x * blockDim.x + threadIdx.x;
    int c = (int)(idx & (HID - 1));
    size_t row = idx >> 10;
    float g = sigmoidf_(glin[idx] + gb[c]);
    float v = qkv[row * 3072 + 2048 + c];
    o2[idx] = tf32r(g * o[idx] + (1.0f - g) * v);
}

// ---------------- gate-mix residual ---------------------------------------
__global__ void gmix_residual_kernel(const float* __restrict__ x, const float* __restrict__ glin,
                                     const float* __restrict__ local, const float* __restrict__ attn,
                                     float* __restrict__ x1) {
    size_t idx = (size_t)blockIdx.x * blockDim.x + threadIdx.x;
    float s = sigmoidf_(glin[idx]);
    x1[idx] = x[idx] + s * local[idx] + (1.0f - s) * attn[idx];
}

// ---------------- swiglu (tf32-rounded output) ----------------------------
__global__ void swiglu_kernel(float* __restrict__ a, const float* __restrict__ b) {
    size_t idx = (size_t)blockIdx.x * blockDim.x + threadIdx.x;
    a[idx] = tf32r(siluf_(a[idx]) * b[idx]);
}

// ---------------- final residual ------------------------------------------
__global__ void add_kernel(const float* __restrict__ a, const float* __restrict__ b,
                           float* __restrict__ o) {
    size_t idx = (size_t)blockIdx.x * blockDim.x + threadIdx.x;
    o[idx] = a[idx] + b[idx];
}

// ---------------- host side ------------------------------------------------
#define TGEMM_SMEM (4 * SBUF * sizeof(float))   // 73728 bytes

static inline void run_gemm(const float* A, int ldA, const float* W, int ldW,
                            float* C, int ldC, int M, int N, int K, bool acc, bool rnd) {
    dim3 grid(N / 128, M / 128);
    if (acc)      tgemm_kernel<true,  false><<<grid, 256, TGEMM_SMEM>>>(A, ldA, W, ldW, C, ldC, K);
    else if (rnd) tgemm_kernel<false, true ><<<grid, 256, TGEMM_SMEM>>>(A, ldA, W, ldW, C, ldC, K);
    else          tgemm_kernel<false, false><<<grid, 256, TGEMM_SMEM>>>(A, ldA, W, ldW, C, ldC, K);
}

extern "C" void kernel_launch(void* const* d_in, const int* in_sizes, int n_in,
                              void* d_out, int out_size) {
    const float* x           = (const float*)d_in[0];
    const float* qkv_w       = (const float*)d_in[1];
    const float* out_proj_w  = (const float*)d_in[2];
    const float* out_gate_w  = (const float*)d_in[3];
    const float* out_gate_b  = (const float*)d_in[4];
    const float* decay_param = (const float*)d_in[5];
    const float* conv_w      = (const float*)d_in[6];
    const float* conv_b      = (const float*)d_in[7];
    const float* pw_w        = (const float*)d_in[8];
    const float* gate_w      = (const float*)d_in[9];
    const float* w1          = (const float*)d_in[10];
    const float* w2          = (const float*)d_in[11];
    const float* w3          = (const float*)d_in[12];
    const float* norm1_w     = (const float*)d_in[13];
    const float* norm2_w     = (const float*)d_in[14];
    float* out = (float*)d_out;

    static int smem_set = 0;
    if (!smem_set) {
        cudaFuncSetAttribute(tgemm_kernel<false, false>,
                             cudaFuncAttributeMaxDynamicSharedMemorySize, (int)TGEMM_SMEM);
        cudaFuncSetAttribute(tgemm_kernel<false, true>,
                             cudaFuncAttributeMaxDynamicSharedMemorySize, (int)TGEMM_SMEM);
        cudaFuncSetAttribute(tgemm_kernel<true, false>,
                             cudaFuncAttributeMaxDynamicSharedMemorySize, (int)TGEMM_SMEM);
        smem_set = 1;
    }

    float* S = nullptr;
    cudaGetSymbolAddress((void**)&S, g_scratch);

    float* g_h    = S + OFF_H;
    float* g_qkv  = S + OFF_QKV;
    float* g_conv = S + OFF_CONV;
    float* g_loc  = S + OFF_LOCAL;
    float* g_rks  = S + OFF_RKS;
    float* g_rkv  = S + OFF_RKV;
    float* g_o    = S + OFF_O;
    float* g_tmp  = S + OFF_TMP;
    float* g_o2   = S + OFF_O2;
    float* g_attn = S + OFF_ATTN;
    float* g_x1   = S + OFF_X1;
    float* g_h2   = S + OFF_H2;
    float* g_ffa  = S + OFF_FFA;
    float* g_ffb  = S + OFF_FFB;
    float* g_ffn  = S + OFF_FFN;
    float* g_cks  = S + OFF_CKS;
    float* g_ckv  = S + OFF_CKV;
    float* g_pks  = S + OFF_PKS;
    float* g_pkv  = S + OFF_PKV;
    float* c_qkvw = S + OFF_WQKV;
    float* c_opw  = S + OFF_WOP;
    float* c_ogw  = S + OFF_WOG;
    float* c_pww  = S + OFF_WPW;
    float* c_gtw  = S + OFF_WGT;
    float* c_w1   = S + OFF_WW1;
    float* c_w2   = S + OFF_WW2;
    float* c_w3   = S + OFF_WW3;

    const int NEH = 256;
    const int GMH = (int)(SZ_MH / NEH);
    const int GMI = (int)(SZ_MI / NEH);

    // 0. round weights to tf32 once per launch (enables CVT-free GEMM loads)
    cvt_tf32_kernel<<<(3 * HID * HID) / 256, 256>>>(qkv_w, c_qkvw, 3 * HID * HID);
    cvt_tf32_kernel<<<(HID * HID) / 256, 256>>>(out_proj_w, c_opw, HID * HID);
    cvt_tf32_kernel<<<(HID * HID) / 256, 256>>>(out_gate_w, c_ogw, HID * HID);
    cvt_tf32_kernel<<<(HID * HID) / 256, 256>>>(pw_w, c_pww, HID * HID);
    cvt_tf32_kernel<<<(2 * HID * HID) / 256, 256>>>(gate_w, c_gtw, 2 * HID * HID);
    cvt_tf32_kernel<<<(INTER * HID) / 256, 256>>>(w1, c_w1, INTER * HID);
    cvt_tf32_kernel<<<(INTER * HID) / 256, 256>>>(w2, c_w2, INTER * HID);
    cvt_tf32_kernel<<<(INTER * HID) / 256, 256>>>(w3, c_w3, INTER * HID);

    // 1. h = rmsnorm(x, norm1_w)  (tf32-rounded output)
    rmsnorm_kernel<<<MROWS, 256>>>(x, norm1_w, g_h);

    // 2. qkv = h @ qkv_w^T
    run_gemm(g_h, HID, c_qkvw, HID, g_qkv, 3 * HID, MROWS, 3 * HID, HID, false, false);

    // 3. conv branch (conv output tf32-rounded; pw output rounded for gate GEMM)
    conv_silu_kernel<<<GMH, NEH>>>(g_h, conv_w, conv_b, g_conv);
    run_gemm(g_conv, HID, c_pww, HID, g_loc, HID, MROWS, HID, HID, false, true);

    // 4. elu+1 on q,k
    eluqk_kernel<<<(int)((size_t)MROWS * 2048 / NEH), NEH>>>(g_qkv);

    // 5. decayed scans
    {
        dim3 gA(HID / 256, NCHUNK, BB);
        scan_chunk_kernel<<<gA, 256>>>(g_qkv, decay_param, g_rks, g_rkv, g_cks, g_ckv);
        dim3 gB(HID / 256, BB);
        scan_carry_kernel<<<gB, 256>>>(decay_param, g_cks, g_ckv, g_pks, g_pkv);
        scan_fix_kernel<<<GMH, NEH>>>(decay_param, g_pks, g_pkv, g_rks, g_rkv);
    }

    // 6. o (tf32-rounded, feeds out_gate GEMM)
    attn_o_kernel<<<MROWS * NH * 32 / 256, 256>>>(g_qkv, g_rks, g_rkv, g_o);

    // 7. out gate
    run_gemm(g_o, HID, c_ogw, HID, g_tmp, HID, MROWS, HID, HID, false, false);
    outgate_mix_kernel<<<GMH, NEH>>>(g_tmp, out_gate_b, g_o, g_qkv, g_o2);

    // 8. attn = o2 @ out_proj^T (rounded: feeds gate GEMM)
    run_gemm(g_o2, HID, c_opw, HID, g_attn, HID, MROWS, HID, HID, false, true);

    // 9. gmix (split-K over concat)
    run_gemm(g_loc,  HID, c_gtw,       2 * HID, g_tmp, HID, MROWS, HID, HID, false, false);
    run_gemm(g_attn, HID, c_gtw + HID, 2 * HID, g_tmp, HID, MROWS, HID, HID, true, false);
    gmix_residual_kernel<<<GMH, NEH>>>(x, g_tmp, g_loc, g_attn, g_x1);

    // 10. FFN
    rmsnorm_kernel<<<MROWS, 256>>>(g_x1, norm2_w, g_h2);
    run_gemm(g_h2, HID, c_w1, HID, g_ffa, INTER, MROWS, INTER, HID, false, false);
    run_gemm(g_h2, HID, c_w2, HID, g_ffb, INTER, MROWS, INTER, HID, false, false);
    swiglu_kernel<<<GMI, NEH>>>(g_ffa, g_ffb);
    run_gemm(g_ffa, INTER, c_w3, INTER, g_ffn, HID, MROWS, HID, INTER, false, false);

    // 11. out = x1 + ffn
    add_kernel<<<GMH, NEH>>>(g_x1, g_ffn, out);
}